// round 4
// baseline (speedup 1.0000x reference)
#include <cuda_runtime.h>
#include <math.h>

// ---------------- problem constants ----------------
#define BATCH   16
#define NTOK    1024          // 32*32 spatial tokens
#define CIN     256
#define INNER   512
#define CTXN    77
#define CTXD    768
#define MTOK    (BATCH*NTOK)  // 16384
#define MCTX    (BATCH*CTXN)  // 1232

// ---------------- scratch (device globals; no allocation) ----------------
__device__ float g_gn1[MTOK*CIN];        // 16 MB
__device__ float g_h  [MTOK*INNER];      // 32 MB
__device__ float g_hn [MTOK*INNER];
__device__ float g_q  [MTOK*INNER];
__device__ float g_k  [MTOK*INNER];
__device__ float g_v  [MTOK*INNER];
__device__ float g_sim[16777216];        // B*N*N = 16M floats, 64 MB
__device__ float g_o  [MTOK*INNER];
__device__ float g_k2 [MCTX*INNER];
__device__ float g_v2 [MCTX*INNER];

// ---------------- GroupNorm 1: x[B,256,32,32] -> token-major gn1[B*N,256] ----------------
__global__ void gn1_kernel(const float* __restrict__ x, const float* __restrict__ gam,
                           const float* __restrict__ bet, float* __restrict__ out)
{
    // grid = B*32 groups, 8 channels * 1024 spatial per group
    int bg = blockIdx.x;
    int b  = bg >> 5, grp = bg & 31;
    const float* xb = x + ((long)b*CIN + grp*8) * NTOK;
    __shared__ float r1[256], r2[256];
    int t = threadIdx.x;
    float s = 0.f, s2 = 0.f;
    for (int i = t; i < 8192; i += 256) { float v = xb[i]; s += v; s2 += v*v; }
    r1[t] = s; r2[t] = s2; __syncthreads();
    for (int o = 128; o > 0; o >>= 1) {
        if (t < o) { r1[t] += r1[t+o]; r2[t] += r2[t+o]; }
        __syncthreads();
    }
    float mean = r1[0] * (1.f/8192.f);
    float var  = r2[0] * (1.f/8192.f) - mean*mean;
    float rstd = rsqrtf(var + 1e-5f);
    for (int i = t; i < 8192; i += 256) {
        int c = grp*8 + (i >> 10);
        int n = i & 1023;
        float v = (xb[i] - mean) * rstd * gam[c] + bet[c];
        out[((long)b*NTOK + n)*CIN + c] = v;
    }
}

// ---------------- GroupNorm 2: h[B*N,512] token-major, 32 groups of 16 ch ----------------
__global__ void gn2_kernel(const float* __restrict__ h, const float* __restrict__ gam,
                           const float* __restrict__ bet, float* __restrict__ out)
{
    int bg = blockIdx.x;
    int b  = bg >> 5, grp = bg & 31;
    const float* hb = h + (long)b*NTOK*INNER;
    float* ob = out + (long)b*NTOK*INNER;
    __shared__ float r1[256], r2[256];
    int t = threadIdx.x;
    float s = 0.f, s2 = 0.f;
    for (int i = t; i < 16384; i += 256) {
        int n = i >> 4, c = grp*16 + (i & 15);
        float v = hb[n*INNER + c]; s += v; s2 += v*v;
    }
    r1[t] = s; r2[t] = s2; __syncthreads();
    for (int o = 128; o > 0; o >>= 1) {
        if (t < o) { r1[t] += r1[t+o]; r2[t] += r2[t+o]; }
        __syncthreads();
    }
    float mean = r1[0] * (1.f/16384.f);
    float var  = r2[0] * (1.f/16384.f) - mean*mean;
    float rstd = rsqrtf(var + 1e-5f);
    for (int i = t; i < 16384; i += 256) {
        int n = i >> 4, c = grp*16 + (i & 15);
        float v = hb[n*INNER + c];
        ob[n*INNER + c] = (v - mean) * rstd * gam[c] + bet[c];
    }
}

// ---------------- generic NT GEMM: C[M,N] = alpha * A[M,K] @ W[N,K]^T (+ epilogue) --------
// modes: 0 store (+bias), 1: C = 2*C + acc, 2: C = C + acc (+bias), 3: transposed +x write
#define EP_STORE 0
#define EP_RES2  1
#define EP_RES1  2
#define EP_TRANSX 3

__global__ __launch_bounds__(256)
void gemm_nt(const float* __restrict__ A, const float* __restrict__ W,
             float* __restrict__ C, const float* __restrict__ bias,
             const float* __restrict__ xin, float* __restrict__ outx,
             int M, int N, int K, float alpha, int mode,
             long long sA, long long sW, long long sC)
{
    A += (long long)blockIdx.z * sA;
    W += (long long)blockIdx.z * sW;
    C += (long long)blockIdx.z * sC;

    __shared__ float As[8][128];
    __shared__ float Ws[8][128];
    int m0 = blockIdx.y * 128, n0 = blockIdx.x * 128;
    int tid = threadIdx.x;
    int tx = tid & 15, ty = tid >> 4;

    float acc[8][8];
    #pragma unroll
    for (int i = 0; i < 8; i++)
        #pragma unroll
        for (int j = 0; j < 8; j++) acc[i][j] = 0.f;

    int lrow = tid >> 1;          // 0..127
    int lseg = (tid & 1) * 4;     // 0 or 4

    for (int k0 = 0; k0 < K; k0 += 8) {
        {
            int gm = m0 + lrow;
            float4 va = make_float4(0.f,0.f,0.f,0.f);
            if (gm < M) va = *(const float4*)&A[(long long)gm*K + k0 + lseg];
            As[lseg+0][lrow] = va.x; As[lseg+1][lrow] = va.y;
            As[lseg+2][lrow] = va.z; As[lseg+3][lrow] = va.w;
        }
        {
            int gn = n0 + lrow;   // N is always a multiple of 128 here
            float4 vw = *(const float4*)&W[(long long)gn*K + k0 + lseg];
            Ws[lseg+0][lrow] = vw.x; Ws[lseg+1][lrow] = vw.y;
            Ws[lseg+2][lrow] = vw.z; Ws[lseg+3][lrow] = vw.w;
        }
        __syncthreads();
        #pragma unroll
        for (int k = 0; k < 8; k++) {
            float a[8], b[8];
            #pragma unroll
            for (int i = 0; i < 8; i++) a[i] = As[k][ty*8 + i];
            #pragma unroll
            for (int j = 0; j < 8; j++) b[j] = Ws[k][tx*8 + j];
            #pragma unroll
            for (int i = 0; i < 8; i++)
                #pragma unroll
                for (int j = 0; j < 8; j++)
                    acc[i][j] += a[i] * b[j];
        }
        __syncthreads();
    }

    #pragma unroll
    for (int i = 0; i < 8; i++) {
        int row = m0 + ty*8 + i;
        if (row < M) {
            #pragma unroll
            for (int j = 0; j < 8; j++) {
                int col = n0 + tx*8 + j;
                float val = alpha * acc[i][j];
                if (bias) val += bias[col];
                long long idx = (long long)row*N + col;
                if (mode == EP_STORE)      C[idx] = val;
                else if (mode == EP_RES2)  C[idx] = 2.f*C[idx] + val;
                else if (mode == EP_RES1)  C[idx] = C[idx] + val;
                else {
                    int bb = row >> 10, n = row & 1023;
                    long long oi = (((long long)bb*CIN + col) << 10) + n;
                    outx[oi] = val + xin[oi];
                }
            }
        }
    }
}

// ---------------- NN GEMM: C[M,N] = A[M,K] @ B[K,N] (batched, plain store) ----------------
__global__ __launch_bounds__(256)
void gemm_nn(const float* __restrict__ A, const float* __restrict__ Bm,
             float* __restrict__ C, int M, int N, int K,
             long long sA, long long sB, long long sC)
{
    A  += (long long)blockIdx.z * sA;
    Bm += (long long)blockIdx.z * sB;
    C  += (long long)blockIdx.z * sC;

    __shared__ float As[8][128];
    __shared__ float Bs[8][128];
    int m0 = blockIdx.y * 128, n0 = blockIdx.x * 128;
    int tid = threadIdx.x;
    int tx = tid & 15, ty = tid >> 4;

    float acc[8][8];
    #pragma unroll
    for (int i = 0; i < 8; i++)
        #pragma unroll
        for (int j = 0; j < 8; j++) acc[i][j] = 0.f;

    int lrow = tid >> 1;
    int lseg = (tid & 1) * 4;
    int brow = tid >> 5;          // 0..7
    int bcol = (tid & 31) * 4;    // 0..124

    for (int k0 = 0; k0 < K; k0 += 8) {
        {
            int gm = m0 + lrow;
            float4 va = make_float4(0.f,0.f,0.f,0.f);
            if (gm < M) va = *(const float4*)&A[(long long)gm*K + k0 + lseg];
            As[lseg+0][lrow] = va.x; As[lseg+1][lrow] = va.y;
            As[lseg+2][lrow] = va.z; As[lseg+3][lrow] = va.w;
        }
        {
            float4 vb = *(const float4*)&Bm[(long long)(k0+brow)*N + n0 + bcol];
            *(float4*)&Bs[brow][bcol] = vb;
        }
        __syncthreads();
        #pragma unroll
        for (int k = 0; k < 8; k++) {
            float a[8], b[8];
            #pragma unroll
            for (int i = 0; i < 8; i++) a[i] = As[k][ty*8 + i];
            #pragma unroll
            for (int j = 0; j < 8; j++) b[j] = Bs[k][tx*8 + j];
            #pragma unroll
            for (int i = 0; i < 8; i++)
                #pragma unroll
                for (int j = 0; j < 8; j++)
                    acc[i][j] += a[i] * b[j];
        }
        __syncthreads();
    }

    #pragma unroll
    for (int i = 0; i < 8; i++) {
        int row = m0 + ty*8 + i;
        if (row < M) {
            #pragma unroll
            for (int j = 0; j < 8; j++) {
                int col = n0 + tx*8 + j;
                C[(long long)row*N + col] = acc[i][j];
            }
        }
    }
}

// ---------------- row softmax over g_sim: 16384 rows x 1024 ----------------
__global__ void softmax_rows(float* __restrict__ S)
{
    long long row = blockIdx.x;
    float* p = S + row * 1024;
    __shared__ float red[256];
    int t = threadIdx.x;
    float v[4];
    float mx = -1e30f;
    #pragma unroll
    for (int i = 0; i < 4; i++) { v[i] = p[t + i*256]; mx = fmaxf(mx, v[i]); }
    red[t] = mx; __syncthreads();
    for (int o = 128; o > 0; o >>= 1) {
        if (t < o) red[t] = fmaxf(red[t], red[t+o]);
        __syncthreads();
    }
    mx = red[0]; __syncthreads();
    float sum = 0.f;
    #pragma unroll
    for (int i = 0; i < 4; i++) { v[i] = __expf(v[i] - mx); sum += v[i]; }
    red[t] = sum; __syncthreads();
    for (int o = 128; o > 0; o >>= 1) {
        if (t < o) red[t] += red[t+o];
        __syncthreads();
    }
    float inv = 1.f / red[0];
    #pragma unroll
    for (int i = 0; i < 4; i++) p[t + i*256] = v[i] * inv;
}

// ---------------- cross-attention core: 8 heads x 64, 77 keys -----------------
// q [B*N,512] (head-major inner), k/v [B*77,512]; out o [B*N,512]
__global__ __launch_bounds__(128)
void ca_attn(const float* __restrict__ q, const float* __restrict__ k,
             const float* __restrict__ v, float* __restrict__ o)
{
    __shared__ float Ks[77][65];
    __shared__ float Vs[77][65];
    __shared__ float Qs[4][64];
    __shared__ float Ps[4][80];

    int b = blockIdx.z, hd = blockIdx.y, qt = blockIdx.x;
    int t = threadIdx.x, w = t >> 5, l = t & 31;

    for (int i = t; i < 77*64; i += 128) {
        int j = i >> 6, d = i & 63;
        long long src = ((long long)(b*CTXN + j))*INNER + hd*64 + d;
        Ks[j][d] = k[src];
        Vs[j][d] = v[src];
    }
    __syncthreads();

    for (int qi = 0; qi < 32; qi++) {
        int qn = qt*128 + w*32 + qi;
        const float* qp = q + ((long long)(b*NTOK + qn))*INNER + hd*64;
        Qs[w][l]    = qp[l];
        Qs[w][l+32] = qp[l+32];
        __syncwarp();

        float sc[3];
        float mx = -1e30f;
        #pragma unroll
        for (int r = 0; r < 3; r++) {
            int j = l + r*32;
            float s = -1e30f;
            if (j < 77) {
                s = 0.f;
                #pragma unroll
                for (int d = 0; d < 64; d++) s += Qs[w][d] * Ks[j][d];
                s *= 0.125f;   // DH^-0.5
            }
            sc[r] = s; mx = fmaxf(mx, s);
        }
        #pragma unroll
        for (int off = 16; off > 0; off >>= 1)
            mx = fmaxf(mx, __shfl_xor_sync(0xFFFFFFFFu, mx, off));

        float sum = 0.f;
        #pragma unroll
        for (int r = 0; r < 3; r++) {
            int j = l + r*32;
            if (j < 77) {
                float e = __expf(sc[r] - mx);
                sum += e;
                Ps[w][j] = e;
            }
        }
        #pragma unroll
        for (int off = 16; off > 0; off >>= 1)
            sum += __shfl_xor_sync(0xFFFFFFFFu, sum, off);
        __syncwarp();

        float inv = 1.f / sum;
        float o0 = 0.f, o1 = 0.f;
        for (int j = 0; j < 77; j++) {
            float pj = Ps[w][j];
            o0 += pj * Vs[j][l];
            o1 += pj * Vs[j][l+32];
        }
        float* op = o + ((long long)(b*NTOK + qn))*INNER + hd*64;
        op[l]    = o0 * inv;
        op[l+32] = o1 * inv;
        __syncwarp();
    }
}

// ---------------- host launch ----------------
extern "C" void kernel_launch(void* const* d_in, const int* in_sizes, int n_in,
                              void* d_out, int out_size)
{
    const float* x      = (const float*)d_in[0];
    const float* ctx    = (const float*)d_in[1];
    const float* gn1_g  = (const float*)d_in[2];
    const float* gn1_b  = (const float*)d_in[3];
    const float* w_in   = (const float*)d_in[4];
    const float* b_in   = (const float*)d_in[5];
    const float* sa_wk  = (const float*)d_in[6];
    const float* sa_wq  = (const float*)d_in[7];
    const float* sa_wv  = (const float*)d_in[8];
    const float* sa_wp  = (const float*)d_in[9];
    const float* sa_gng = (const float*)d_in[10];
    const float* sa_gnb = (const float*)d_in[11];
    const float* ca_wq  = (const float*)d_in[12];
    const float* ca_wk  = (const float*)d_in[13];
    const float* ca_wv  = (const float*)d_in[14];
    const float* ca_wo  = (const float*)d_in[15];
    const float* ca_bo  = (const float*)d_in[16];
    const float* w_out  = (const float*)d_in[17];
    const float* b_out  = (const float*)d_in[18];
    float* out = (float*)d_out;

    float *p_gn1, *p_h, *p_hn, *p_q, *p_k, *p_v, *p_sim, *p_o, *p_k2, *p_v2;
    cudaGetSymbolAddress((void**)&p_gn1, g_gn1);
    cudaGetSymbolAddress((void**)&p_h,   g_h);
    cudaGetSymbolAddress((void**)&p_hn,  g_hn);
    cudaGetSymbolAddress((void**)&p_q,   g_q);
    cudaGetSymbolAddress((void**)&p_k,   g_k);
    cudaGetSymbolAddress((void**)&p_v,   g_v);
    cudaGetSymbolAddress((void**)&p_sim, g_sim);
    cudaGetSymbolAddress((void**)&p_o,   g_o);
    cudaGetSymbolAddress((void**)&p_k2,  g_k2);
    cudaGetSymbolAddress((void**)&p_v2,  g_v2);

    const float simScale = 0.044194173824159216f; // 512^-0.5

    // 1. GroupNorm1 -> token-major
    gn1_kernel<<<BATCH*32, 256>>>(x, gn1_g, gn1_b, p_gn1);

    // 2. conv_in: h = gn1 @ w_in^T + b_in   [16384,256]x[512,256]^T
    gemm_nt<<<dim3(4,128,1), 256>>>(p_gn1, w_in, p_h, b_in, nullptr, nullptr,
                                    MTOK, INNER, CIN, 1.f, EP_STORE, 0,0,0);

    // 3. SA groupnorm
    gn2_kernel<<<BATCH*32, 256>>>(p_h, sa_gng, sa_gnb, p_hn);

    // 4. q/k/v projections [16384,512]x[512,512]^T
    gemm_nt<<<dim3(4,128,1), 256>>>(p_hn, sa_wq, p_q, nullptr, nullptr, nullptr,
                                    MTOK, INNER, INNER, 1.f, EP_STORE, 0,0,0);
    gemm_nt<<<dim3(4,128,1), 256>>>(p_hn, sa_wk, p_k, nullptr, nullptr, nullptr,
                                    MTOK, INNER, INNER, 1.f, EP_STORE, 0,0,0);
    gemm_nt<<<dim3(4,128,1), 256>>>(p_hn, sa_wv, p_v, nullptr, nullptr, nullptr,
                                    MTOK, INNER, INNER, 1.f, EP_STORE, 0,0,0);

    // 5. sim = scale * q @ k^T per batch  (NT, batched over z)
    gemm_nt<<<dim3(8,8,BATCH), 256>>>(p_q, p_k, p_sim, nullptr, nullptr, nullptr,
                                      NTOK, NTOK, INNER, simScale, EP_STORE,
                                      (long long)NTOK*INNER, (long long)NTOK*INNER,
                                      (long long)NTOK*NTOK);

    // 6. softmax over rows
    softmax_rows<<<MTOK, 256>>>(p_sim);

    // 7. o = attn @ v per batch (NN, batched)
    gemm_nn<<<dim3(4,8,BATCH), 256>>>(p_sim, p_v, p_o, NTOK, INNER, NTOK,
                                      (long long)NTOK*NTOK, (long long)NTOK*INNER,
                                      (long long)NTOK*INNER);

    // 8. h = 2*h + o @ sa_wp^T
    gemm_nt<<<dim3(4,128,1), 256>>>(p_o, sa_wp, p_h, nullptr, nullptr, nullptr,
                                    MTOK, INNER, INNER, 1.f, EP_RES2, 0,0,0);

    // 9. CA q = h @ ca_wq^T
    gemm_nt<<<dim3(4,128,1), 256>>>(p_h, ca_wq, p_q, nullptr, nullptr, nullptr,
                                    MTOK, INNER, INNER, 1.f, EP_STORE, 0,0,0);

    // 10/11. CA k,v = ctx @ w^T   [1232,768]x[512,768]^T
    gemm_nt<<<dim3(4,10,1), 256>>>(ctx, ca_wk, p_k2, nullptr, nullptr, nullptr,
                                   MCTX, INNER, CTXD, 1.f, EP_STORE, 0,0,0);
    gemm_nt<<<dim3(4,10,1), 256>>>(ctx, ca_wv, p_v2, nullptr, nullptr, nullptr,
                                   MCTX, INNER, CTXD, 1.f, EP_STORE, 0,0,0);

    // 12. CA attention core
    ca_attn<<<dim3(8,8,BATCH), 128>>>(p_q, p_k2, p_v2, p_o);

    // 13. h = h + (o @ ca_wo^T + ca_bo)
    gemm_nt<<<dim3(4,128,1), 256>>>(p_o, ca_wo, p_h, ca_bo, nullptr, nullptr,
                                    MTOK, INNER, INNER, 1.f, EP_RES1, 0,0,0);

    // 14. out = transpose(h @ w_out^T + b_out) + x   (NCHW write)
    gemm_nt<<<dim3(2,128,1), 256>>>(p_h, w_out, nullptr, b_out, x, out,
                                    MTOK, CIN, INNER, 1.f, EP_TRANSX, 0,0,0);
}

// round 7
// speedup vs baseline: 2.9118x; 2.9118x over previous
#include <cuda_runtime.h>
#include <cstdint>
#include <math.h>

// ---------------- problem constants ----------------
#define BATCH   16
#define NTOK    1024
#define CIN     256
#define INNER   512
#define CTXN    77
#define CTXD    768
#define MTOK    (BATCH*NTOK)  // 16384
#define MCTX    (BATCH*CTXN)  // 1232

// ---------------- scratch (device globals; no allocation) ----------------
__device__ float g_gn1[MTOK*CIN];
__device__ float g_h  [MTOK*INNER];
__device__ float g_hn [MTOK*INNER];
__device__ float g_q  [MTOK*INNER];
__device__ float g_k  [MTOK*INNER];
__device__ float g_v  [MTOK*INNER];      // holds vT: [B][512][1024]
__device__ float g_sim[16777216];        // B*N*N
__device__ float g_o  [MTOK*INNER];
__device__ float g_k2 [MCTX*INNER];
__device__ float g_v2 [MCTX*INNER];

// =======================================================================
// GroupNorm 1: x[B,256,32,32] -> token-major gn1[B*N,256]
// =======================================================================
__global__ void gn1_kernel(const float* __restrict__ x, const float* __restrict__ gam,
                           const float* __restrict__ bet, float* __restrict__ out)
{
    int bg = blockIdx.x;
    int b  = bg >> 5, grp = bg & 31;
    const float* xb = x + ((long)b*CIN + grp*8) * NTOK;
    __shared__ float r1[256], r2[256];
    int t = threadIdx.x;
    float s = 0.f, s2 = 0.f;
    for (int i = t; i < 8192; i += 256) { float v = xb[i]; s += v; s2 += v*v; }
    r1[t] = s; r2[t] = s2; __syncthreads();
    for (int o = 128; o > 0; o >>= 1) {
        if (t < o) { r1[t] += r1[t+o]; r2[t] += r2[t+o]; }
        __syncthreads();
    }
    float mean = r1[0] * (1.f/8192.f);
    float var  = r2[0] * (1.f/8192.f) - mean*mean;
    float rstd = rsqrtf(var + 1e-5f);
    for (int i = t; i < 8192; i += 256) {
        int c = grp*8 + (i >> 10);
        int n = i & 1023;
        float v = (xb[i] - mean) * rstd * gam[c] + bet[c];
        out[((long)b*NTOK + n)*CIN + c] = v;
    }
}

// =======================================================================
// GroupNorm 2: h[B*N,512] token-major, 32 groups of 16 channels
// =======================================================================
__global__ void gn2_kernel(const float* __restrict__ h, const float* __restrict__ gam,
                           const float* __restrict__ bet, float* __restrict__ out)
{
    int bg = blockIdx.x;
    int b  = bg >> 5, grp = bg & 31;
    const float* hb = h + (long)b*NTOK*INNER;
    float* ob = out + (long)b*NTOK*INNER;
    __shared__ float r1[256], r2[256];
    int t = threadIdx.x;
    float s = 0.f, s2 = 0.f;
    for (int i = t; i < 16384; i += 256) {
        int n = i >> 4, c = grp*16 + (i & 15);
        float v = hb[n*INNER + c]; s += v; s2 += v*v;
    }
    r1[t] = s; r2[t] = s2; __syncthreads();
    for (int o = 128; o > 0; o >>= 1) {
        if (t < o) { r1[t] += r1[t+o]; r2[t] += r2[t+o]; }
        __syncthreads();
    }
    float mean = r1[0] * (1.f/16384.f);
    float var  = r2[0] * (1.f/16384.f) - mean*mean;
    float rstd = rsqrtf(var + 1e-5f);
    for (int i = t; i < 16384; i += 256) {
        int n = i >> 4, c = grp*16 + (i & 15);
        float v = hb[n*INNER + c];
        ob[n*INNER + c] = (v - mean) * rstd * gam[c] + bet[c];
    }
}

// =======================================================================
// row softmax: 16384 rows x 1024
// =======================================================================
__global__ void softmax_rows(float* __restrict__ S)
{
    long long row = blockIdx.x;
    float* p = S + row * 1024;
    __shared__ float red[256];
    int t = threadIdx.x;
    float v[4];
    float mx = -1e30f;
    #pragma unroll
    for (int i = 0; i < 4; i++) { v[i] = p[t + i*256]; mx = fmaxf(mx, v[i]); }
    red[t] = mx; __syncthreads();
    for (int o = 128; o > 0; o >>= 1) {
        if (t < o) red[t] = fmaxf(red[t], red[t+o]);
        __syncthreads();
    }
    mx = red[0]; __syncthreads();
    float sum = 0.f;
    #pragma unroll
    for (int i = 0; i < 4; i++) { v[i] = __expf(v[i] - mx); sum += v[i]; }
    red[t] = sum; __syncthreads();
    for (int o = 128; o > 0; o >>= 1) {
        if (t < o) red[t] += red[t+o];
        __syncthreads();
    }
    float inv = 1.f / red[0];
    #pragma unroll
    for (int i = 0; i < 4; i++) p[t + i*256] = v[i] * inv;
}

// =======================================================================
// cross-attention core: 8 heads x 64d, 77 keys
// =======================================================================
__global__ __launch_bounds__(128)
void ca_attn(const float* __restrict__ q, const float* __restrict__ k,
             const float* __restrict__ v, float* __restrict__ o)
{
    __shared__ float Ks[77][65];
    __shared__ float Vs[77][65];
    __shared__ float Qs[4][64];
    __shared__ float Ps[4][80];

    int b = blockIdx.z, hd = blockIdx.y, qt = blockIdx.x;
    int t = threadIdx.x, w = t >> 5, l = t & 31;

    for (int i = t; i < 77*64; i += 128) {
        int j = i >> 6, d = i & 63;
        long long src = ((long long)(b*CTXN + j))*INNER + hd*64 + d;
        Ks[j][d] = k[src];
        Vs[j][d] = v[src];
    }
    __syncthreads();

    for (int qi = 0; qi < 32; qi++) {
        int qn = qt*128 + w*32 + qi;
        const float* qp = q + ((long long)(b*NTOK + qn))*INNER + hd*64;
        Qs[w][l]    = qp[l];
        Qs[w][l+32] = qp[l+32];
        __syncwarp();

        float sc[3];
        float mx = -1e30f;
        #pragma unroll
        for (int r = 0; r < 3; r++) {
            int j = l + r*32;
            float s = -1e30f;
            if (j < 77) {
                s = 0.f;
                #pragma unroll
                for (int d = 0; d < 64; d++) s += Qs[w][d] * Ks[j][d];
                s *= 0.125f;
            }
            sc[r] = s; mx = fmaxf(mx, s);
        }
        #pragma unroll
        for (int off = 16; off > 0; off >>= 1)
            mx = fmaxf(mx, __shfl_xor_sync(0xFFFFFFFFu, mx, off));

        float sum = 0.f;
        #pragma unroll
        for (int r = 0; r < 3; r++) {
            int j = l + r*32;
            if (j < 77) {
                float e = __expf(sc[r] - mx);
                sum += e;
                Ps[w][j] = e;
            }
        }
        #pragma unroll
        for (int off = 16; off > 0; off >>= 1)
            sum += __shfl_xor_sync(0xFFFFFFFFu, sum, off);
        __syncwarp();

        float inv = 1.f / sum;
        float o0 = 0.f, o1 = 0.f;
        for (int j = 0; j < 77; j++) {
            float pj = Ps[w][j];
            o0 += pj * Vs[j][l];
            o1 += pj * Vs[j][l+32];
        }
        float* op = o + ((long long)(b*NTOK + qn))*INNER + hd*64;
        op[l]    = o0 * inv;
        op[l+32] = o1 * inv;
        __syncwarp();
    }
}

// =======================================================================
// tf32 mma.sync NT GEMM: C[M,N] = alpha * A[M,K] @ W[N,K]^T (+ epilogues)
// 128x128 CTA tile, BK=32, 8 warps x (64x32) warp tiles, m16n8k8 HMMA,
// double-buffered cp.async, pad-4 smem (conflict-free fragment LDS).
// =======================================================================
#define EP_STORE  0
#define EP_RES2   1
#define EP_RES1   2
#define EP_TRANSX 3
#define EP_STORET 4

#define BK    32
#define PADW  36                    // 32 + 4 floats; bank = (4*row+col)%32 -> perm
#define TSZ   (128*PADW)            // floats per tile
#define BUFSZ (2*TSZ)               // A tile + W tile
#define SMEM_MMA (2*BUFSZ*4)        // 2 buffers, bytes = 73728

__device__ __forceinline__ void cp16(uint32_t dst, const float* src) {
    asm volatile("cp.async.cg.shared.global [%0], [%1], 16;" :: "r"(dst), "l"(src));
}
__device__ __forceinline__ uint32_t smem_u32(const void* p) {
    uint32_t a;
    asm("{ .reg .u64 t; cvta.to.shared.u64 t, %1; cvt.u32.u64 %0, t; }" : "=r"(a) : "l"(p));
    return a;
}
__device__ __forceinline__ uint32_t f2tf32(float f) {
    uint32_t r;
    asm("cvt.rna.tf32.f32 %0, %1;" : "=r"(r) : "f"(f));
    return r;
}
__device__ __forceinline__ void mma_tf32(float* c, const uint32_t* a, const uint32_t* b) {
    asm volatile("mma.sync.aligned.m16n8k8.row.col.f32.tf32.tf32.f32 "
                 "{%0,%1,%2,%3}, {%4,%5,%6,%7}, {%8,%9}, {%0,%1,%2,%3};"
                 : "+f"(c[0]), "+f"(c[1]), "+f"(c[2]), "+f"(c[3])
                 : "r"(a[0]), "r"(a[1]), "r"(a[2]), "r"(a[3]), "r"(b[0]), "r"(b[1]));
}

__global__ __launch_bounds__(256)
void gemm_mma(const float* __restrict__ A, const float* __restrict__ W,
              float* __restrict__ C, const float* __restrict__ bias,
              const float* __restrict__ xin, float* __restrict__ outx,
              int M, int N, int K, float alpha, int mode,
              long long sA, long long sW, long long sC)
{
    extern __shared__ float smem[];
    A += (long long)blockIdx.z * sA;
    W += (long long)blockIdx.z * sW;
    C += (long long)blockIdx.z * sC;

    const int m0 = blockIdx.y * 128, n0 = blockIdx.x * 128;
    const int tid = threadIdx.x;
    const int wid = tid >> 5, lane = tid & 31;
    const int wm = wid & 1, wn = wid >> 1;       // 2 x 4 warp grid, 64x32 each
    const int rowmax = M - m0;                   // >0
    const uint32_t sbase = smem_u32(smem);

    const float* Ag = A + (long long)m0 * K;
    const float* Wg = W + (long long)n0 * K;

    float acc[4][4][4];
    #pragma unroll
    for (int i = 0; i < 4; i++)
        #pragma unroll
        for (int j = 0; j < 4; j++)
            #pragma unroll
            for (int r = 0; r < 4; r++) acc[i][j][r] = 0.f;

    const int nch = K >> 5;

    // ---- async tile loader ----
    auto load_tiles = [&](int buf, int c) {
        uint32_t sA4 = sbase + buf * (BUFSZ * 4);
        uint32_t sW4 = sA4 + TSZ * 4;
        const float* Agk = Ag + c * BK;
        const float* Wgk = Wg + c * BK;
        #pragma unroll
        for (int i = 0; i < 4; i++) {
            int f = tid + 256 * i;            // 0..1023
            int r = f >> 3, c4 = f & 7;       // row, float4 idx
            int ra = (r < rowmax) ? r : (rowmax - 1);
            cp16(sA4 + (r * PADW + c4 * 4) * 4, Agk + (long long)ra * K + c4 * 4);
        }
        #pragma unroll
        for (int i = 0; i < 4; i++) {
            int f = tid + 256 * i;
            int r = f >> 3, c4 = f & 7;
            cp16(sW4 + (r * PADW + c4 * 4) * 4, Wgk + (long long)r * K + c4 * 4);
        }
        asm volatile("cp.async.commit_group;" ::: "memory");
    };

    load_tiles(0, 0);

    const int frow = lane >> 2;     // 0..7
    const int fcol = lane & 3;      // 0..3

    for (int c = 0; c < nch; c++) {
        int buf = c & 1;
        if (c + 1 < nch) {
            load_tiles(buf ^ 1, c + 1);
            asm volatile("cp.async.wait_group 1;" ::: "memory");
        } else {
            asm volatile("cp.async.wait_group 0;" ::: "memory");
        }
        __syncthreads();

        const float* As = smem + buf * BUFSZ;
        const float* Ws = As + TSZ;
        const float* Aw = As + wm * 64 * PADW;
        const float* Ww = Ws + wn * 32 * PADW;

        #pragma unroll
        for (int kk = 0; kk < 4; kk++) {
            const int kb = kk * 8;
            uint32_t a[4][4], b[4][2];
            #pragma unroll
            for (int mf = 0; mf < 4; mf++) {
                const float* base = Aw + (mf * 16) * PADW + kb;
                a[mf][0] = f2tf32(base[frow * PADW + fcol]);
                a[mf][1] = f2tf32(base[(frow + 8) * PADW + fcol]);
                a[mf][2] = f2tf32(base[frow * PADW + fcol + 4]);
                a[mf][3] = f2tf32(base[(frow + 8) * PADW + fcol + 4]);
            }
            #pragma unroll
            for (int nf = 0; nf < 4; nf++) {
                const float* base = Ww + (nf * 8 + frow) * PADW + kb;
                b[nf][0] = f2tf32(base[fcol]);
                b[nf][1] = f2tf32(base[fcol + 4]);
            }
            #pragma unroll
            for (int mf = 0; mf < 4; mf++)
                #pragma unroll
                for (int nf = 0; nf < 4; nf++)
                    mma_tf32(acc[mf][nf], a[mf], b[nf]);
        }
        __syncthreads();
    }

    // ---- epilogue ----
    #pragma unroll
    for (int mf = 0; mf < 4; mf++) {
        #pragma unroll
        for (int nf = 0; nf < 4; nf++) {
            int rg = m0 + wm * 64 + mf * 16 + frow;
            int cg = n0 + wn * 32 + nf * 8 + 2 * fcol;
            #pragma unroll
            for (int half = 0; half < 2; half++) {
                int row = rg + half * 8;
                if (row >= M) continue;
                float v0 = alpha * acc[mf][nf][half * 2 + 0];
                float v1 = alpha * acc[mf][nf][half * 2 + 1];
                if (bias) { v0 += bias[cg]; v1 += bias[cg + 1]; }
                if (mode == EP_TRANSX) {
                    int bb = row >> 10, n = row & 1023;
                    long long o0 = (((long long)bb * CIN + cg) << 10) + n;
                    long long o1 = o0 + 1024;
                    outx[o0] = v0 + xin[o0];
                    outx[o1] = v1 + xin[o1];
                } else if (mode == EP_STORET) {
                    int bb = row >> 10, n = row & 1023;
                    long long o0 = (((long long)bb * N + cg) << 10) + n;
                    C[o0]        = v0;
                    C[o0 + 1024] = v1;
                } else {
                    float* cp = C + (long long)row * N + cg;
                    if (mode == EP_RES2)      { v0 += 2.f * cp[0]; v1 += 2.f * cp[1]; }
                    else if (mode == EP_RES1) { v0 += cp[0];       v1 += cp[1]; }
                    cp[0] = v0; cp[1] = v1;
                }
            }
        }
    }
}

// =======================================================================
// host launch
// =======================================================================
extern "C" void kernel_launch(void* const* d_in, const int* in_sizes, int n_in,
                              void* d_out, int out_size)
{
    const float* x      = (const float*)d_in[0];
    const float* ctx    = (const float*)d_in[1];
    const float* gn1_g  = (const float*)d_in[2];
    const float* gn1_b  = (const float*)d_in[3];
    const float* w_in   = (const float*)d_in[4];
    const float* b_in   = (const float*)d_in[5];
    const float* sa_wk  = (const float*)d_in[6];
    const float* sa_wq  = (const float*)d_in[7];
    const float* sa_wv  = (const float*)d_in[8];
    const float* sa_wp  = (const float*)d_in[9];
    const float* sa_gng = (const float*)d_in[10];
    const float* sa_gnb = (const float*)d_in[11];
    const float* ca_wq  = (const float*)d_in[12];
    const float* ca_wk  = (const float*)d_in[13];
    const float* ca_wv  = (const float*)d_in[14];
    const float* ca_wo  = (const float*)d_in[15];
    const float* ca_bo  = (const float*)d_in[16];
    const float* w_out  = (const float*)d_in[17];
    const float* b_out  = (const float*)d_in[18];
    float* out = (float*)d_out;

    float *p_gn1, *p_h, *p_hn, *p_q, *p_k, *p_v, *p_sim, *p_o, *p_k2, *p_v2;
    cudaGetSymbolAddress((void**)&p_gn1, g_gn1);
    cudaGetSymbolAddress((void**)&p_h,   g_h);
    cudaGetSymbolAddress((void**)&p_hn,  g_hn);
    cudaGetSymbolAddress((void**)&p_q,   g_q);
    cudaGetSymbolAddress((void**)&p_k,   g_k);
    cudaGetSymbolAddress((void**)&p_v,   g_v);
    cudaGetSymbolAddress((void**)&p_sim, g_sim);
    cudaGetSymbolAddress((void**)&p_o,   g_o);
    cudaGetSymbolAddress((void**)&p_k2,  g_k2);
    cudaGetSymbolAddress((void**)&p_v2,  g_v2);

    cudaFuncSetAttribute(gemm_mma, cudaFuncAttributeMaxDynamicSharedMemorySize, SMEM_MMA);

    const float simScale = 0.044194173824159216f; // 512^-0.5

    // 1. GroupNorm1 -> token-major
    gn1_kernel<<<BATCH*32, 256>>>(x, gn1_g, gn1_b, p_gn1);

    // 2. conv_in: h = gn1 @ w_in^T + b_in
    gemm_mma<<<dim3(4,128,1), 256, SMEM_MMA>>>(p_gn1, w_in, p_h, b_in, nullptr, nullptr,
                                               MTOK, INNER, CIN, 1.f, EP_STORE, 0,0,0);

    // 3. SA groupnorm
    gn2_kernel<<<BATCH*32, 256>>>(p_h, sa_gng, sa_gnb, p_hn);

    // 4. q/k/v projections (v stored transposed: vT[b][c][n])
    gemm_mma<<<dim3(4,128,1), 256, SMEM_MMA>>>(p_hn, sa_wq, p_q, nullptr, nullptr, nullptr,
                                               MTOK, INNER, INNER, 1.f, EP_STORE, 0,0,0);
    gemm_mma<<<dim3(4,128,1), 256, SMEM_MMA>>>(p_hn, sa_wk, p_k, nullptr, nullptr, nullptr,
                                               MTOK, INNER, INNER, 1.f, EP_STORE, 0,0,0);
    gemm_mma<<<dim3(4,128,1), 256, SMEM_MMA>>>(p_hn, sa_wv, p_v, nullptr, nullptr, nullptr,
                                               MTOK, INNER, INNER, 1.f, EP_STORET, 0,0,0);

    // 5. sim = scale * q @ k^T (batched)
    gemm_mma<<<dim3(8,8,BATCH), 256, SMEM_MMA>>>(p_q, p_k, p_sim, nullptr, nullptr, nullptr,
                                                 NTOK, NTOK, INNER, simScale, EP_STORE,
                                                 (long long)NTOK*INNER, (long long)NTOK*INNER,
                                                 (long long)NTOK*NTOK);

    // 6. softmax
    softmax_rows<<<MTOK, 256>>>(p_sim);

    // 7. o = attn @ v  == NT with W = vT (batched)
    gemm_mma<<<dim3(4,8,BATCH), 256, SMEM_MMA>>>(p_sim, p_v, p_o, nullptr, nullptr, nullptr,
                                                 NTOK, INNER, NTOK, 1.f, EP_STORE,
                                                 (long long)NTOK*NTOK, (long long)INNER*NTOK,
                                                 (long long)NTOK*INNER);

    // 8. h = 2*h + o @ sa_wp^T
    gemm_mma<<<dim3(4,128,1), 256, SMEM_MMA>>>(p_o, sa_wp, p_h, nullptr, nullptr, nullptr,
                                               MTOK, INNER, INNER, 1.f, EP_RES2, 0,0,0);

    // 9. CA q = h @ ca_wq^T
    gemm_mma<<<dim3(4,128,1), 256, SMEM_MMA>>>(p_h, ca_wq, p_q, nullptr, nullptr, nullptr,
                                               MTOK, INNER, INNER, 1.f, EP_STORE, 0,0,0);

    // 10/11. CA k,v = ctx @ w^T
    gemm_mma<<<dim3(4,10,1), 256, SMEM_MMA>>>(ctx, ca_wk, p_k2, nullptr, nullptr, nullptr,
                                              MCTX, INNER, CTXD, 1.f, EP_STORE, 0,0,0);
    gemm_mma<<<dim3(4,10,1), 256, SMEM_MMA>>>(ctx, ca_wv, p_v2, nullptr, nullptr, nullptr,
                                              MCTX, INNER, CTXD, 1.f, EP_STORE, 0,0,0);

    // 12. CA attention core
    ca_attn<<<dim3(8,8,BATCH), 128>>>(p_q, p_k2, p_v2, p_o);

    // 13. h = h + (o @ ca_wo^T + ca_bo)
    gemm_mma<<<dim3(4,128,1), 256, SMEM_MMA>>>(p_o, ca_wo, p_h, ca_bo, nullptr, nullptr,
                                               MTOK, INNER, INNER, 1.f, EP_RES1, 0,0,0);

    // 14. out = transpose(h @ w_out^T + b_out) + x
    gemm_mma<<<dim3(2,128,1), 256, SMEM_MMA>>>(p_h, w_out, nullptr, b_out, x, out,
                                               MTOK, CIN, INNER, 1.f, EP_TRANSX, 0,0,0);
}

// round 8
// speedup vs baseline: 2.9763x; 1.0221x over previous
#include <cuda_runtime.h>
#include <cstdint>
#include <math.h>

// ---------------- problem constants ----------------
#define BATCH   16
#define NTOK    1024
#define CIN     256
#define INNER   512
#define CTXN    77
#define CTXD    768
#define MTOK    (BATCH*NTOK)  // 16384
#define MCTX    (BATCH*CTXN)  // 1232

// rounded-weight scratch offsets
#define OFF_WIN  0
#define OFF_SAQ  131072
#define OFF_SAK  393216
#define OFF_SAV  655360
#define OFF_SAP  917504
#define OFF_CAQ  1179648
#define OFF_CAK  1441792
#define OFF_CAV  1835008
#define OFF_CAO  2228224
#define OFF_WOUT 2490368
#define WTOT     2621440

// ---------------- scratch (device globals; no allocation) ----------------
__device__ float g_gn1[MTOK*CIN];
__device__ float g_h  [MTOK*INNER];
__device__ float g_hn [MTOK*INNER];
__device__ float g_q  [MTOK*INNER];
__device__ float g_k  [MTOK*INNER];
__device__ float g_v  [MTOK*INNER];      // SA: vT [B][512][1024]; later CA: v2t [128][64][96]
__device__ float g_sim[16777216];        // SA: B*N*N probs; later CA: [128][1024][96]
__device__ float g_o  [MTOK*INNER];
__device__ float g_k2 [MCTX*INNER];
__device__ float g_wr [WTOT];            // pre-rounded weights

// ---------------- tf32 helpers ----------------
__device__ __forceinline__ uint32_t f2tf32(float f) {
    uint32_t r;
    asm("cvt.rna.tf32.f32 %0, %1;" : "=r"(r) : "f"(f));
    return r;
}
__device__ __forceinline__ float rtf(float f) { return __uint_as_float(f2tf32(f)); }

__device__ __forceinline__ void cp16(uint32_t dst, const float* src) {
    asm volatile("cp.async.cg.shared.global [%0], [%1], 16;" :: "r"(dst), "l"(src));
}
__device__ __forceinline__ uint32_t smem_u32(const void* p) {
    uint32_t a;
    asm("{ .reg .u64 t; cvta.to.shared.u64 t, %1; cvt.u32.u64 %0, t; }" : "=r"(a) : "l"(p));
    return a;
}
__device__ __forceinline__ void mma_tf32(float* c, const uint32_t* a, const uint32_t* b) {
    asm volatile("mma.sync.aligned.m16n8k8.row.col.f32.tf32.tf32.f32 "
                 "{%0,%1,%2,%3}, {%4,%5,%6,%7}, {%8,%9}, {%0,%1,%2,%3};"
                 : "+f"(c[0]), "+f"(c[1]), "+f"(c[2]), "+f"(c[3])
                 : "r"(a[0]), "r"(a[1]), "r"(a[2]), "r"(a[3]), "r"(b[0]), "r"(b[1]));
}

// ---------------- weight pre-rounding ----------------
__global__ void wround_kernel(const float* __restrict__ w0, const float* __restrict__ w1,
                              const float* __restrict__ w2, const float* __restrict__ w3,
                              const float* __restrict__ w4, const float* __restrict__ w5,
                              const float* __restrict__ w6, const float* __restrict__ w7,
                              const float* __restrict__ w8, const float* __restrict__ w9,
                              float* __restrict__ dst)
{
    int i = blockIdx.x * 1024 + threadIdx.x;
    const float* s; int off;
    if      (i < OFF_SAQ)  { s = w0; off = OFF_WIN;  }
    else if (i < OFF_SAK)  { s = w1; off = OFF_SAQ;  }
    else if (i < OFF_SAV)  { s = w2; off = OFF_SAK;  }
    else if (i < OFF_SAP)  { s = w3; off = OFF_SAV;  }
    else if (i < OFF_CAQ)  { s = w4; off = OFF_SAP;  }
    else if (i < OFF_CAK)  { s = w5; off = OFF_CAQ;  }
    else if (i < OFF_CAV)  { s = w6; off = OFF_CAK;  }
    else if (i < OFF_CAO)  { s = w7; off = OFF_CAV;  }
    else if (i < OFF_WOUT) { s = w8; off = OFF_CAO;  }
    else                   { s = w9; off = OFF_WOUT; }
    dst[i] = rtf(s[i - off]);
}

// ---------------- GroupNorm 1 (rounded store) ----------------
__global__ void gn1_kernel(const float* __restrict__ x, const float* __restrict__ gam,
                           const float* __restrict__ bet, float* __restrict__ out)
{
    int bg = blockIdx.x;
    int b  = bg >> 5, grp = bg & 31;
    const float* xb = x + ((long)b*CIN + grp*8) * NTOK;
    __shared__ float r1[256], r2[256];
    int t = threadIdx.x;
    float s = 0.f, s2 = 0.f;
    for (int i = t; i < 8192; i += 256) { float v = xb[i]; s += v; s2 += v*v; }
    r1[t] = s; r2[t] = s2; __syncthreads();
    for (int o = 128; o > 0; o >>= 1) {
        if (t < o) { r1[t] += r1[t+o]; r2[t] += r2[t+o]; }
        __syncthreads();
    }
    float mean = r1[0] * (1.f/8192.f);
    float var  = r2[0] * (1.f/8192.f) - mean*mean;
    float rstd = rsqrtf(var + 1e-5f);
    for (int i = t; i < 8192; i += 256) {
        int c = grp*8 + (i >> 10);
        int n = i & 1023;
        float v = (xb[i] - mean) * rstd * gam[c] + bet[c];
        out[((long)b*NTOK + n)*CIN + c] = rtf(v);
    }
}

// ---------------- GroupNorm 2 (rounded store) ----------------
__global__ void gn2_kernel(const float* __restrict__ h, const float* __restrict__ gam,
                           const float* __restrict__ bet, float* __restrict__ out)
{
    int bg = blockIdx.x;
    int b  = bg >> 5, grp = bg & 31;
    const float* hb = h + (long)b*NTOK*INNER;
    float* ob = out + (long)b*NTOK*INNER;
    __shared__ float r1[256], r2[256];
    int t = threadIdx.x;
    float s = 0.f, s2 = 0.f;
    for (int i = t; i < 16384; i += 256) {
        int n = i >> 4, c = grp*16 + (i & 15);
        float v = hb[n*INNER + c]; s += v; s2 += v*v;
    }
    r1[t] = s; r2[t] = s2; __syncthreads();
    for (int o = 128; o > 0; o >>= 1) {
        if (t < o) { r1[t] += r1[t+o]; r2[t] += r2[t+o]; }
        __syncthreads();
    }
    float mean = r1[0] * (1.f/16384.f);
    float var  = r2[0] * (1.f/16384.f) - mean*mean;
    float rstd = rsqrtf(var + 1e-5f);
    for (int i = t; i < 16384; i += 256) {
        int n = i >> 4, c = grp*16 + (i & 15);
        float v = hb[n*INNER + c];
        ob[n*INNER + c] = rtf((v - mean) * rstd * gam[c] + bet[c]);
    }
}

// ---------------- SA row softmax: 16384 rows x 1024 (rounded store) ----------------
__global__ void softmax_rows(float* __restrict__ S)
{
    long long row = blockIdx.x;
    float* p = S + row * 1024;
    __shared__ float red[256];
    int t = threadIdx.x;
    float v[4];
    float mx = -1e30f;
    #pragma unroll
    for (int i = 0; i < 4; i++) { v[i] = p[t + i*256]; mx = fmaxf(mx, v[i]); }
    red[t] = mx; __syncthreads();
    for (int o = 128; o > 0; o >>= 1) {
        if (t < o) red[t] = fmaxf(red[t], red[t+o]);
        __syncthreads();
    }
    mx = red[0]; __syncthreads();
    float sum = 0.f;
    #pragma unroll
    for (int i = 0; i < 4; i++) { v[i] = __expf(v[i] - mx); sum += v[i]; }
    red[t] = sum; __syncthreads();
    for (int o = 128; o > 0; o >>= 1) {
        if (t < o) red[t] += red[t+o];
        __syncthreads();
    }
    float inv = 1.f / red[0];
    #pragma unroll
    for (int i = 0; i < 4; i++) p[t + i*256] = rtf(v[i] * inv);
}

// ---------------- CA softmax: 131072 rows x 77 (ld 96), zero-pad 77..95 ----------------
__global__ void softmax77(float* __restrict__ S)
{
    int warp = (blockIdx.x * 256 + threadIdx.x) >> 5;
    int l = threadIdx.x & 31;
    float* p = S + (long long)warp * 96;
    float v0 = p[l];
    float v1 = p[l + 32];
    float v2 = (l + 64 < 77) ? p[l + 64] : -1e30f;
    float mx = fmaxf(v0, fmaxf(v1, v2));
    #pragma unroll
    for (int off = 16; off > 0; off >>= 1)
        mx = fmaxf(mx, __shfl_xor_sync(0xFFFFFFFFu, mx, off));
    float e0 = __expf(v0 - mx), e1 = __expf(v1 - mx);
    float e2 = (l + 64 < 77) ? __expf(v2 - mx) : 0.f;
    float sum = e0 + e1 + e2;
    #pragma unroll
    for (int off = 16; off > 0; off >>= 1)
        sum += __shfl_xor_sync(0xFFFFFFFFu, sum, off);
    float inv = 1.f / sum;
    p[l]      = rtf(e0 * inv);
    p[l + 32] = rtf(e1 * inv);
    p[l + 64] = (l + 64 < 77) ? rtf(e2 * inv) : 0.f;
}

// =======================================================================
// tf32 mma.sync NT GEMM: C[M,N] = alpha * A[M,K] @ W[N,K]^T (+ epilogues)
// Operands pre-rounded to tf32 (CVTA=1 converts A-side fragments on the fly).
// =======================================================================
#define EP_STORE   0
#define EP_RES2    1
#define EP_RES1    2
#define EP_TRANSX  3
#define EP_STORET  4
#define EP_STORECV 5

#define BK    32
#define PADW  36
#define TSZ   (128*PADW)
#define BUFSZ (2*TSZ)
#define SMEM_MMA (2*BUFSZ*4)        // 73728 bytes

template<int CVTA>
__global__ __launch_bounds__(256, 2)
void gemm_mma(const float* __restrict__ A, const float* __restrict__ W,
              float* __restrict__ C, const float* __restrict__ bias,
              const float* __restrict__ xin, float* __restrict__ outx,
              int M, int K, int lda, int ldw, int ldc,
              int wrowmax, int nvalid, float alpha, int mode, int roundC,
              int HZ, long long sAb, long long sAh,
              long long sWb, long long sWh, long long sCb, long long sCh)
{
    extern __shared__ float smem[];
    {
        int z = blockIdx.z;
        int zb = z, zh = 0;
        if (HZ > 1) { zb = z / HZ; zh = z - zb * HZ; }
        A += zb*sAb + zh*sAh;
        W += zb*sWb + zh*sWh;
        C += zb*sCb + zh*sCh;
    }

    const int m0 = blockIdx.y * 128, n0 = blockIdx.x * 128;
    const int tid = threadIdx.x;
    const int wid = tid >> 5, lane = tid & 31;
    const int wm = wid & 1, wn = wid >> 1;
    const int rowmax = M - m0;
    const uint32_t sbase = smem_u32(smem);

    const float* Ag = A + (long long)m0 * lda;

    float acc[4][4][4];
    #pragma unroll
    for (int i = 0; i < 4; i++)
        #pragma unroll
        for (int j = 0; j < 4; j++)
            #pragma unroll
            for (int r = 0; r < 4; r++) acc[i][j][r] = 0.f;

    const int nch = K >> 5;

    auto load_tiles = [&](int buf, int c) {
        uint32_t sA4 = sbase + buf * (BUFSZ * 4);
        uint32_t sW4 = sA4 + TSZ * 4;
        const float* Agk = Ag + c * BK;
        #pragma unroll
        for (int i = 0; i < 4; i++) {
            int f = tid + 256 * i;
            int r = f >> 3, c4 = f & 7;
            int ra = (r < rowmax) ? r : (rowmax - 1);
            cp16(sA4 + (r * PADW + c4 * 4) * 4, Agk + (long long)ra * lda + c4 * 4);
        }
        #pragma unroll
        for (int i = 0; i < 4; i++) {
            int f = tid + 256 * i;
            int r = f >> 3, c4 = f & 7;
            int rw = (n0 + r < wrowmax) ? (n0 + r) : (wrowmax - 1);
            cp16(sW4 + (r * PADW + c4 * 4) * 4, W + (long long)rw * ldw + c * BK + c4 * 4);
        }
        asm volatile("cp.async.commit_group;" ::: "memory");
    };

    load_tiles(0, 0);

    const int frow = lane >> 2;
    const int fcol = lane & 3;

    for (int c = 0; c < nch; c++) {
        int buf = c & 1;
        if (c + 1 < nch) {
            load_tiles(buf ^ 1, c + 1);
            asm volatile("cp.async.wait_group 1;" ::: "memory");
        } else {
            asm volatile("cp.async.wait_group 0;" ::: "memory");
        }
        __syncthreads();

        const uint32_t* As = (const uint32_t*)smem + buf * BUFSZ;
        const uint32_t* Ws = As + TSZ;
        const uint32_t* Aw = As + wm * 64 * PADW;
        const uint32_t* Ww = Ws + wn * 32 * PADW;

        #pragma unroll
        for (int kk = 0; kk < 4; kk++) {
            const int kb = kk * 8;
            uint32_t a[4][4], b[4][2];
            #pragma unroll
            for (int mf = 0; mf < 4; mf++) {
                const uint32_t* base = Aw + (mf * 16) * PADW + kb;
                a[mf][0] = base[frow * PADW + fcol];
                a[mf][1] = base[(frow + 8) * PADW + fcol];
                a[mf][2] = base[frow * PADW + fcol + 4];
                a[mf][3] = base[(frow + 8) * PADW + fcol + 4];
                if (CVTA) {
                    a[mf][0] = f2tf32(__uint_as_float(a[mf][0]));
                    a[mf][1] = f2tf32(__uint_as_float(a[mf][1]));
                    a[mf][2] = f2tf32(__uint_as_float(a[mf][2]));
                    a[mf][3] = f2tf32(__uint_as_float(a[mf][3]));
                }
            }
            #pragma unroll
            for (int nf = 0; nf < 4; nf++) {
                const uint32_t* base = Ww + (nf * 8 + frow) * PADW + kb;
                b[nf][0] = base[fcol];
                b[nf][1] = base[fcol + 4];
            }
            #pragma unroll
            for (int mf = 0; mf < 4; mf++)
                #pragma unroll
                for (int nf = 0; nf < 4; nf++)
                    mma_tf32(acc[mf][nf], a[mf], b[nf]);
        }
        __syncthreads();
    }

    // ---- epilogue ----
    #pragma unroll
    for (int mf = 0; mf < 4; mf++) {
        #pragma unroll
        for (int nf = 0; nf < 4; nf++) {
            int rg  = m0 + wm * 64 + mf * 16 + frow;
            int cg  = n0 + wn * 32 + nf * 8 + 2 * fcol;
            bool g0 = cg < nvalid, g1 = cg + 1 < nvalid;
            #pragma unroll
            for (int half = 0; half < 2; half++) {
                int row = rg + half * 8;
                if (row >= M) continue;
                float v0 = alpha * acc[mf][nf][half * 2 + 0];
                float v1 = alpha * acc[mf][nf][half * 2 + 1];
                if (bias) {
                    if (g0) v0 += bias[cg];
                    if (g1) v1 += bias[cg + 1];
                }
                if (roundC) { v0 = rtf(v0); v1 = rtf(v1); }
                if (mode == EP_TRANSX) {
                    int bb = row >> 10, n = row & 1023;
                    long long o0 = (((long long)bb * CIN + cg) << 10) + n;
                    if (g0) outx[o0]        = v0 + xin[o0];
                    if (g1) outx[o0 + 1024] = v1 + xin[o0 + 1024];
                } else if (mode == EP_STORET) {
                    int bb = row >> 10, n = row & 1023;
                    long long o0 = (((long long)bb * INNER + cg) << 10) + n;
                    C[o0]        = v0;
                    C[o0 + 1024] = v1;
                } else if (mode == EP_STORECV) {
                    // v2t[(b*8+h)*64*96 + d*96 + j]; row = b*77+j, col = h*64+d
                    int bb = row / 77, j = row - bb * 77;
                    int h0 = cg >> 6, d0 = cg & 63;
                    int h1 = (cg + 1) >> 6, d1 = (cg + 1) & 63;
                    C[((long long)(bb * 8 + h0) * 64 + d0) * 96 + j] = v0;
                    C[((long long)(bb * 8 + h1) * 64 + d1) * 96 + j] = v1;
                } else {
                    float* cp = C + (long long)row * ldc + cg;
                    if (mode == EP_RES2)      { if (g0) v0 += 2.f * cp[0]; if (g1) v1 += 2.f * cp[1]; }
                    else if (mode == EP_RES1) { if (g0) v0 += cp[0];       if (g1) v1 += cp[1]; }
                    if (g0) cp[0] = v0;
                    if (g1) cp[1] = v1;
                }
            }
        }
    }
}

// =======================================================================
// host launch
// =======================================================================
extern "C" void kernel_launch(void* const* d_in, const int* in_sizes, int n_in,
                              void* d_out, int out_size)
{
    const float* x      = (const float*)d_in[0];
    const float* ctx    = (const float*)d_in[1];
    const float* gn1_g  = (const float*)d_in[2];
    const float* gn1_b  = (const float*)d_in[3];
    const float* w_in   = (const float*)d_in[4];
    const float* b_in   = (const float*)d_in[5];
    const float* sa_wk  = (const float*)d_in[6];
    const float* sa_wq  = (const float*)d_in[7];
    const float* sa_wv  = (const float*)d_in[8];
    const float* sa_wp  = (const float*)d_in[9];
    const float* sa_gng = (const float*)d_in[10];
    const float* sa_gnb = (const float*)d_in[11];
    const float* ca_wq  = (const float*)d_in[12];
    const float* ca_wk  = (const float*)d_in[13];
    const float* ca_wv  = (const float*)d_in[14];
    const float* ca_wo  = (const float*)d_in[15];
    const float* ca_bo  = (const float*)d_in[16];
    const float* w_out  = (const float*)d_in[17];
    const float* b_out  = (const float*)d_in[18];
    float* out = (float*)d_out;

    float *p_gn1, *p_h, *p_hn, *p_q, *p_k, *p_v, *p_sim, *p_o, *p_k2, *p_wr;
    cudaGetSymbolAddress((void**)&p_gn1, g_gn1);
    cudaGetSymbolAddress((void**)&p_h,   g_h);
    cudaGetSymbolAddress((void**)&p_hn,  g_hn);
    cudaGetSymbolAddress((void**)&p_q,   g_q);
    cudaGetSymbolAddress((void**)&p_k,   g_k);
    cudaGetSymbolAddress((void**)&p_v,   g_v);
    cudaGetSymbolAddress((void**)&p_sim, g_sim);
    cudaGetSymbolAddress((void**)&p_o,   g_o);
    cudaGetSymbolAddress((void**)&p_k2,  g_k2);
    cudaGetSymbolAddress((void**)&p_wr,  g_wr);

    cudaFuncSetAttribute(gemm_mma<0>, cudaFuncAttributeMaxDynamicSharedMemorySize, SMEM_MMA);
    cudaFuncSetAttribute(gemm_mma<1>, cudaFuncAttributeMaxDynamicSharedMemorySize, SMEM_MMA);

    const float simScale = 0.044194173824159216f; // 512^-0.5

    // 0. pre-round weights
    wround_kernel<<<WTOT/1024, 1024>>>(w_in, sa_wq, sa_wk, sa_wv, sa_wp,
                                       ca_wq, ca_wk, ca_wv, ca_wo, w_out, p_wr);

    // 1. GroupNorm1 -> token-major (rounded)
    gn1_kernel<<<BATCH*32, 256>>>(x, gn1_g, gn1_b, p_gn1);

    // 2. conv_in: h = gn1 @ w_in^T + b_in (full precision store)
    gemm_mma<0><<<dim3(4,128,1), 256, SMEM_MMA>>>(p_gn1, p_wr+OFF_WIN, p_h, b_in, nullptr, nullptr,
        MTOK, CIN, CIN, CIN, INNER, INNER, INNER, 1.f, EP_STORE, 0, 1, 0,0, 0,0, 0,0);

    // 3. SA groupnorm (rounded)
    gn2_kernel<<<BATCH*32, 256>>>(p_h, sa_gng, sa_gnb, p_hn);

    // 4. q/k/v projections (rounded; v stored transposed per batch)
    gemm_mma<0><<<dim3(4,128,1), 256, SMEM_MMA>>>(p_hn, p_wr+OFF_SAQ, p_q, nullptr, nullptr, nullptr,
        MTOK, INNER, INNER, INNER, INNER, INNER, INNER, 1.f, EP_STORE, 1, 1, 0,0, 0,0, 0,0);
    gemm_mma<0><<<dim3(4,128,1), 256, SMEM_MMA>>>(p_hn, p_wr+OFF_SAK, p_k, nullptr, nullptr, nullptr,
        MTOK, INNER, INNER, INNER, INNER, INNER, INNER, 1.f, EP_STORE, 1, 1, 0,0, 0,0, 0,0);
    gemm_mma<0><<<dim3(4,128,1), 256, SMEM_MMA>>>(p_hn, p_wr+OFF_SAV, p_v, nullptr, nullptr, nullptr,
        MTOK, INNER, INNER, INNER, INNER, INNER, INNER, 1.f, EP_STORET, 1, 1, 0,0, 0,0, 0,0);

    // 5. sim = scale * q @ k^T (batched; full precision, softmax rounds)
    gemm_mma<0><<<dim3(8,8,BATCH), 256, SMEM_MMA>>>(p_q, p_k, p_sim, nullptr, nullptr, nullptr,
        NTOK, INNER, INNER, INNER, NTOK, NTOK, NTOK, simScale, EP_STORE, 0, 1,
        (long long)NTOK*INNER, 0, (long long)NTOK*INNER, 0, (long long)NTOK*NTOK, 0);

    // 6. SA softmax (rounded)
    softmax_rows<<<MTOK, 256>>>(p_sim);

    // 7. o = P @ vT^T (batched NT; rounded)
    gemm_mma<0><<<dim3(4,8,BATCH), 256, SMEM_MMA>>>(p_sim, p_v, p_o, nullptr, nullptr, nullptr,
        NTOK, NTOK, NTOK, NTOK, INNER, INNER, INNER, 1.f, EP_STORE, 1, 1,
        (long long)NTOK*NTOK, 0, (long long)INNER*NTOK, 0, (long long)NTOK*INNER, 0);

    // 8. h = 2*h + o @ sa_wp^T (full precision)
    gemm_mma<0><<<dim3(4,128,1), 256, SMEM_MMA>>>(p_o, p_wr+OFF_SAP, p_h, nullptr, nullptr, nullptr,
        MTOK, INNER, INNER, INNER, INNER, INNER, INNER, 1.f, EP_RES2, 0, 1, 0,0, 0,0, 0,0);

    // 9. CA q = h @ ca_wq^T (A unrounded -> CVTA; rounded store)
    gemm_mma<1><<<dim3(4,128,1), 256, SMEM_MMA>>>(p_h, p_wr+OFF_CAQ, p_q, nullptr, nullptr, nullptr,
        MTOK, INNER, INNER, INNER, INNER, INNER, INNER, 1.f, EP_STORE, 1, 1, 0,0, 0,0, 0,0);

    // 10/11. CA k (rounded), v (per-head transposed into g_v, rounded)
    gemm_mma<1><<<dim3(4,10,1), 256, SMEM_MMA>>>(ctx, p_wr+OFF_CAK, p_k2, nullptr, nullptr, nullptr,
        MCTX, CTXD, CTXD, CTXD, INNER, INNER, INNER, 1.f, EP_STORE, 1, 1, 0,0, 0,0, 0,0);
    gemm_mma<1><<<dim3(4,10,1), 256, SMEM_MMA>>>(ctx, p_wr+OFF_CAV, p_v, nullptr, nullptr, nullptr,
        MCTX, CTXD, CTXD, CTXD, INNER, INNER, INNER, 1.f, EP_STORECV, 1, 1, 0,0, 0,0, 0,0);

    // 12. CA sim2 = 0.125 * Q_head @ K2_head^T  [128 batches of (1024 x 77 x 64)]
    gemm_mma<0><<<dim3(1,8,128), 256, SMEM_MMA>>>(p_q, p_k2, p_sim, nullptr, nullptr, nullptr,
        NTOK, 64, INNER, INNER, 96, CTXN, CTXN, 0.125f, EP_STORE, 0, 8,
        (long long)NTOK*INNER, 64, (long long)CTXN*INNER, 64,
        (long long)8*NTOK*96, (long long)NTOK*96);

    // 13. CA softmax over 77 (rounded, zero-pads to 96)
    softmax77<<<16384, 256>>>(p_sim);

    // 14. CA o = P @ v2t^T  [128 batches of (1024 x 64 x 96)] (rounded)
    gemm_mma<0><<<dim3(1,8,128), 256, SMEM_MMA>>>(p_sim, p_v, p_o, nullptr, nullptr, nullptr,
        NTOK, 96, 96, 96, INNER, 64, 64, 1.f, EP_STORE, 1, 8,
        (long long)8*NTOK*96, (long long)NTOK*96, (long long)8*64*96, (long long)64*96,
        (long long)NTOK*INNER, 64);

    // 15. h = h + (o @ ca_wo^T + ca_bo) (full precision)
    gemm_mma<0><<<dim3(4,128,1), 256, SMEM_MMA>>>(p_o, p_wr+OFF_CAO, p_h, ca_bo, nullptr, nullptr,
        MTOK, INNER, INNER, INNER, INNER, INNER, INNER, 1.f, EP_RES1, 0, 1, 0,0, 0,0, 0,0);

    // 16. out = transpose(h @ w_out^T + b_out) + x (A unrounded -> CVTA)
    gemm_mma<1><<<dim3(2,128,1), 256, SMEM_MMA>>>(p_h, p_wr+OFF_WOUT, nullptr, b_out, x, out,
        MTOK, INNER, INNER, INNER, CIN, CIN, CIN, 1.f, EP_TRANSX, 0, 1, 0,0, 0,0, 0,0);
}

// round 9
// speedup vs baseline: 2.9910x; 1.0049x over previous
#include <cuda_runtime.h>
#include <cstdint>
#include <math.h>

// ---------------- problem constants ----------------
#define BATCH   16
#define NTOK    1024
#define CIN     256
#define INNER   512
#define CTXN    77
#define CTXD    768
#define MTOK    (BATCH*NTOK)  // 16384
#define MCTX    (BATCH*CTXN)  // 1232

// rounded-weight scratch offsets
#define OFF_WIN  0
#define OFF_SAQ  131072
#define OFF_SAK  393216
#define OFF_SAV  655360
#define OFF_SAP  917504
#define OFF_CAQ  1179648
#define OFF_CAK  1441792
#define OFF_CAV  1835008
#define OFF_CAO  2228224
#define OFF_WOUT 2490368
#define WTOT     2621440

// ---------------- scratch (device globals; no allocation) ----------------
__device__ float g_gn1[MTOK*CIN];
__device__ float g_h  [MTOK*INNER];
__device__ float g_hn [MTOK*INNER];
__device__ float g_q  [MTOK*INNER];
__device__ float g_k  [MTOK*INNER];
__device__ float g_v  [MTOK*INNER];      // SA: vT [B][512][1024]; later CA: v2t [128][64][96]
__device__ float g_sim[16777216];        // SA: B*N*N probs; later CA: [128][1024][96]
__device__ float g_o  [MTOK*INNER];
__device__ float g_k2 [MCTX*INNER];
__device__ float g_wr [WTOT];            // pre-rounded weights

// ---------------- tf32 helpers ----------------
__device__ __forceinline__ uint32_t f2tf32(float f) {
    uint32_t r;
    asm("cvt.rna.tf32.f32 %0, %1;" : "=r"(r) : "f"(f));
    return r;
}
__device__ __forceinline__ float rtf(float f) { return __uint_as_float(f2tf32(f)); }

__device__ __forceinline__ void cp16(uint32_t dst, const float* src) {
    asm volatile("cp.async.cg.shared.global [%0], [%1], 16;" :: "r"(dst), "l"(src));
}
__device__ __forceinline__ uint32_t smem_u32(const void* p) {
    uint32_t a;
    asm("{ .reg .u64 t; cvta.to.shared.u64 t, %1; cvt.u32.u64 %0, t; }" : "=r"(a) : "l"(p));
    return a;
}
__device__ __forceinline__ void mma_tf32(float* c, const uint32_t* a, const uint32_t* b) {
    asm volatile("mma.sync.aligned.m16n8k8.row.col.f32.tf32.tf32.f32 "
                 "{%0,%1,%2,%3}, {%4,%5,%6,%7}, {%8,%9}, {%0,%1,%2,%3};"
                 : "+f"(c[0]), "+f"(c[1]), "+f"(c[2]), "+f"(c[3])
                 : "r"(a[0]), "r"(a[1]), "r"(a[2]), "r"(a[3]), "r"(b[0]), "r"(b[1]));
}

// ---------------- weight pre-rounding ----------------
__global__ void wround_kernel(const float* __restrict__ w0, const float* __restrict__ w1,
                              const float* __restrict__ w2, const float* __restrict__ w3,
                              const float* __restrict__ w4, const float* __restrict__ w5,
                              const float* __restrict__ w6, const float* __restrict__ w7,
                              const float* __restrict__ w8, const float* __restrict__ w9,
                              float* __restrict__ dst)
{
    int i = blockIdx.x * 1024 + threadIdx.x;
    const float* s; int off;
    if      (i < OFF_SAQ)  { s = w0; off = OFF_WIN;  }
    else if (i < OFF_SAK)  { s = w1; off = OFF_SAQ;  }
    else if (i < OFF_SAV)  { s = w2; off = OFF_SAK;  }
    else if (i < OFF_SAP)  { s = w3; off = OFF_SAV;  }
    else if (i < OFF_CAQ)  { s = w4; off = OFF_SAP;  }
    else if (i < OFF_CAK)  { s = w5; off = OFF_CAQ;  }
    else if (i < OFF_CAV)  { s = w6; off = OFF_CAK;  }
    else if (i < OFF_CAO)  { s = w7; off = OFF_CAV;  }
    else if (i < OFF_WOUT) { s = w8; off = OFF_CAO;  }
    else                   { s = w9; off = OFF_WOUT; }
    dst[i] = rtf(s[i - off]);
}

// ---------------- GroupNorm 1 (single pass via smem cache; rounded store) ----------------
__global__ void gn1_kernel(const float* __restrict__ x, const float* __restrict__ gam,
                           const float* __restrict__ bet, float* __restrict__ out)
{
    extern __shared__ float cache[];     // 8192 floats
    int bg = blockIdx.x;
    int b  = bg >> 5, grp = bg & 31;
    const float* xb = x + ((long)b*CIN + grp*8) * NTOK;
    __shared__ float r1[256], r2[256];
    int t = threadIdx.x;
    float s = 0.f, s2 = 0.f;
    for (int i = t; i < 8192; i += 256) {
        float v = xb[i]; cache[i] = v; s += v; s2 += v*v;
    }
    r1[t] = s; r2[t] = s2; __syncthreads();
    for (int o = 128; o > 0; o >>= 1) {
        if (t < o) { r1[t] += r1[t+o]; r2[t] += r2[t+o]; }
        __syncthreads();
    }
    float mean = r1[0] * (1.f/8192.f);
    float var  = r2[0] * (1.f/8192.f) - mean*mean;
    float rstd = rsqrtf(var + 1e-5f);
    for (int i = t; i < 8192; i += 256) {
        int c = grp*8 + (i >> 10);
        int n = i & 1023;
        float v = (cache[i] - mean) * rstd * gam[c] + bet[c];
        out[((long)b*NTOK + n)*CIN + c] = rtf(v);
    }
}

// ---------------- GroupNorm 2 (single pass via smem cache; rounded store) ----------------
__global__ void gn2_kernel(const float* __restrict__ h, const float* __restrict__ gam,
                           const float* __restrict__ bet, float* __restrict__ out)
{
    extern __shared__ float cache[];     // 16384 floats
    int bg = blockIdx.x;
    int b  = bg >> 5, grp = bg & 31;
    const float* hb = h + (long)b*NTOK*INNER;
    float* ob = out + (long)b*NTOK*INNER;
    __shared__ float r1[256], r2[256];
    int t = threadIdx.x;
    float s = 0.f, s2 = 0.f;
    for (int i = t; i < 16384; i += 256) {
        int n = i >> 4, c = grp*16 + (i & 15);
        float v = hb[n*INNER + c];
        cache[i] = v; s += v; s2 += v*v;
    }
    r1[t] = s; r2[t] = s2; __syncthreads();
    for (int o = 128; o > 0; o >>= 1) {
        if (t < o) { r1[t] += r1[t+o]; r2[t] += r2[t+o]; }
        __syncthreads();
    }
    float mean = r1[0] * (1.f/16384.f);
    float var  = r2[0] * (1.f/16384.f) - mean*mean;
    float rstd = rsqrtf(var + 1e-5f);
    for (int i = t; i < 16384; i += 256) {
        int n = i >> 4, c = grp*16 + (i & 15);
        ob[n*INNER + c] = rtf((cache[i] - mean) * rstd * gam[c] + bet[c]);
    }
}

// ---------------- SA row softmax: 16384 rows x 1024 (rounded store) ----------------
__global__ void softmax_rows(float* __restrict__ S)
{
    long long row = blockIdx.x;
    float* p = S + row * 1024;
    __shared__ float red[256];
    int t = threadIdx.x;
    float v[4];
    float mx = -1e30f;
    #pragma unroll
    for (int i = 0; i < 4; i++) { v[i] = p[t + i*256]; mx = fmaxf(mx, v[i]); }
    red[t] = mx; __syncthreads();
    for (int o = 128; o > 0; o >>= 1) {
        if (t < o) red[t] = fmaxf(red[t], red[t+o]);
        __syncthreads();
    }
    mx = red[0]; __syncthreads();
    float sum = 0.f;
    #pragma unroll
    for (int i = 0; i < 4; i++) { v[i] = __expf(v[i] - mx); sum += v[i]; }
    red[t] = sum; __syncthreads();
    for (int o = 128; o > 0; o >>= 1) {
        if (t < o) red[t] += red[t+o];
        __syncthreads();
    }
    float inv = 1.f / red[0];
    #pragma unroll
    for (int i = 0; i < 4; i++) p[t + i*256] = rtf(v[i] * inv);
}

// ---------------- CA softmax: 131072 rows x 77 (ld 96), zero-pad 77..95 ----------------
__global__ void softmax77(float* __restrict__ S)
{
    int warp = (blockIdx.x * 256 + threadIdx.x) >> 5;
    int l = threadIdx.x & 31;
    float* p = S + (long long)warp * 96;
    float v0 = p[l];
    float v1 = p[l + 32];
    float v2 = (l + 64 < 77) ? p[l + 64] : -1e30f;
    float mx = fmaxf(v0, fmaxf(v1, v2));
    #pragma unroll
    for (int off = 16; off > 0; off >>= 1)
        mx = fmaxf(mx, __shfl_xor_sync(0xFFFFFFFFu, mx, off));
    float e0 = __expf(v0 - mx), e1 = __expf(v1 - mx);
    float e2 = (l + 64 < 77) ? __expf(v2 - mx) : 0.f;
    float sum = e0 + e1 + e2;
    #pragma unroll
    for (int off = 16; off > 0; off >>= 1)
        sum += __shfl_xor_sync(0xFFFFFFFFu, sum, off);
    float inv = 1.f / sum;
    p[l]      = rtf(e0 * inv);
    p[l + 32] = rtf(e1 * inv);
    p[l + 64] = (l + 64 < 77) ? rtf(e2 * inv) : 0.f;
}

// =======================================================================
// tf32 mma.sync NT GEMM: C[M,N] = alpha * A[M,K] @ W[N,K]^T (+ epilogues)
// 3-stage cp.async pipeline, ONE __syncthreads per k-chunk.
// =======================================================================
#define EP_STORE   0
#define EP_RES2    1
#define EP_RES1    2
#define EP_TRANSX  3
#define EP_STORET  4
#define EP_STORECV 5

#define BK    32
#define PADW  36
#define TSZ   (128*PADW)
#define BUFSZ (2*TSZ)
#define NSTAGE 3
#define SMEM_MMA (NSTAGE*BUFSZ*4)   // 110592 bytes -> 2 CTAs/SM

template<int CVTA>
__global__ __launch_bounds__(256, 2)
void gemm_mma(const float* __restrict__ A, const float* __restrict__ W,
              float* __restrict__ C, const float* __restrict__ bias,
              const float* __restrict__ xin, float* __restrict__ outx,
              int M, int K, int lda, int ldw, int ldc,
              int wrowmax, int nvalid, float alpha, int mode, int roundC,
              int HZ, long long sAb, long long sAh,
              long long sWb, long long sWh, long long sCb, long long sCh)
{
    extern __shared__ float smem[];
    {
        int z = blockIdx.z;
        int zb = z, zh = 0;
        if (HZ > 1) { zb = z / HZ; zh = z - zb * HZ; }
        A += zb*sAb + zh*sAh;
        W += zb*sWb + zh*sWh;
        C += zb*sCb + zh*sCh;
    }

    const int m0 = blockIdx.y * 128, n0 = blockIdx.x * 128;
    const int tid = threadIdx.x;
    const int wid = tid >> 5, lane = tid & 31;
    const int wm = wid & 1, wn = wid >> 1;
    const int rowmax = M - m0;
    const uint32_t sbase = smem_u32(smem);

    const float* Ag = A + (long long)m0 * lda;

    float acc[4][4][4];
    #pragma unroll
    for (int i = 0; i < 4; i++)
        #pragma unroll
        for (int j = 0; j < 4; j++)
            #pragma unroll
            for (int r = 0; r < 4; r++) acc[i][j][r] = 0.f;

    const int nch = K >> 5;

    auto load_tiles = [&](int buf, int c) {
        uint32_t sA4 = sbase + buf * (BUFSZ * 4);
        uint32_t sW4 = sA4 + TSZ * 4;
        const float* Agk = Ag + c * BK;
        #pragma unroll
        for (int i = 0; i < 4; i++) {
            int f = tid + 256 * i;
            int r = f >> 3, c4 = f & 7;
            int ra = (r < rowmax) ? r : (rowmax - 1);
            cp16(sA4 + (r * PADW + c4 * 4) * 4, Agk + (long long)ra * lda + c4 * 4);
        }
        #pragma unroll
        for (int i = 0; i < 4; i++) {
            int f = tid + 256 * i;
            int r = f >> 3, c4 = f & 7;
            int rw = (n0 + r < wrowmax) ? (n0 + r) : (wrowmax - 1);
            cp16(sW4 + (r * PADW + c4 * 4) * 4, W + (long long)rw * ldw + c * BK + c4 * 4);
        }
        asm volatile("cp.async.commit_group;" ::: "memory");
    };

    // prologue: prefetch chunks 0 and 1 (nch >= 2 for all call sites)
    load_tiles(0, 0);
    load_tiles(1, 1);

    const int frow = lane >> 2;
    const int fcol = lane & 3;

    int buf = 0;       // buffer holding chunk c
    int lb  = 2;       // buffer to fill next
    for (int c = 0; c < nch; c++) {
        asm volatile("cp.async.wait_group 1;" ::: "memory");  // chunk c resident
        __syncthreads();                                       // all compute on lb finished last iter
        if (c + 2 < nch) {
            load_tiles(lb, c + 2);
        } else {
            asm volatile("cp.async.commit_group;" ::: "memory"); // keep group count uniform
        }

        const uint32_t* As = (const uint32_t*)smem + buf * BUFSZ;
        const uint32_t* Ws = As + TSZ;
        const uint32_t* Aw = As + wm * 64 * PADW;
        const uint32_t* Ww = Ws + wn * 32 * PADW;

        #pragma unroll
        for (int kk = 0; kk < 4; kk++) {
            const int kb = kk * 8;
            uint32_t a[4][4], b[4][2];
            #pragma unroll
            for (int mf = 0; mf < 4; mf++) {
                const uint32_t* base = Aw + (mf * 16) * PADW + kb;
                a[mf][0] = base[frow * PADW + fcol];
                a[mf][1] = base[(frow + 8) * PADW + fcol];
                a[mf][2] = base[frow * PADW + fcol + 4];
                a[mf][3] = base[(frow + 8) * PADW + fcol + 4];
                if (CVTA) {
                    a[mf][0] = f2tf32(__uint_as_float(a[mf][0]));
                    a[mf][1] = f2tf32(__uint_as_float(a[mf][1]));
                    a[mf][2] = f2tf32(__uint_as_float(a[mf][2]));
                    a[mf][3] = f2tf32(__uint_as_float(a[mf][3]));
                }
            }
            #pragma unroll
            for (int nf = 0; nf < 4; nf++) {
                const uint32_t* base = Ww + (nf * 8 + frow) * PADW + kb;
                b[nf][0] = base[fcol];
                b[nf][1] = base[fcol + 4];
            }
            #pragma unroll
            for (int mf = 0; mf < 4; mf++)
                #pragma unroll
                for (int nf = 0; nf < 4; nf++)
                    mma_tf32(acc[mf][nf], a[mf], b[nf]);
        }
        buf = (buf == NSTAGE-1) ? 0 : buf + 1;
        lb  = (lb  == NSTAGE-1) ? 0 : lb  + 1;
    }

    // ---- epilogue ----
    #pragma unroll
    for (int mf = 0; mf < 4; mf++) {
        #pragma unroll
        for (int nf = 0; nf < 4; nf++) {
            int rg  = m0 + wm * 64 + mf * 16 + frow;
            int cg  = n0 + wn * 32 + nf * 8 + 2 * fcol;
            bool g0 = cg < nvalid, g1 = cg + 1 < nvalid;
            #pragma unroll
            for (int half = 0; half < 2; half++) {
                int row = rg + half * 8;
                if (row >= M) continue;
                float v0 = alpha * acc[mf][nf][half * 2 + 0];
                float v1 = alpha * acc[mf][nf][half * 2 + 1];
                if (bias) {
                    if (g0) v0 += bias[cg];
                    if (g1) v1 += bias[cg + 1];
                }
                if (roundC) { v0 = rtf(v0); v1 = rtf(v1); }
                if (mode == EP_TRANSX) {
                    int bb = row >> 10, n = row & 1023;
                    long long o0 = (((long long)bb * CIN + cg) << 10) + n;
                    if (g0) outx[o0]        = v0 + xin[o0];
                    if (g1) outx[o0 + 1024] = v1 + xin[o0 + 1024];
                } else if (mode == EP_STORET) {
                    int bb = row >> 10, n = row & 1023;
                    long long o0 = (((long long)bb * INNER + cg) << 10) + n;
                    C[o0]        = v0;
                    C[o0 + 1024] = v1;
                } else if (mode == EP_STORECV) {
                    int bb = row / 77, j = row - bb * 77;
                    int h0 = cg >> 6, d0 = cg & 63;
                    int h1 = (cg + 1) >> 6, d1 = (cg + 1) & 63;
                    C[((long long)(bb * 8 + h0) * 64 + d0) * 96 + j] = v0;
                    C[((long long)(bb * 8 + h1) * 64 + d1) * 96 + j] = v1;
                } else {
                    float* cp = C + (long long)row * ldc + cg;
                    if (mode == EP_RES2)      { if (g0) v0 += 2.f * cp[0]; if (g1) v1 += 2.f * cp[1]; }
                    else if (mode == EP_RES1) { if (g0) v0 += cp[0];       if (g1) v1 += cp[1]; }
                    if (g0) cp[0] = v0;
                    if (g1) cp[1] = v1;
                }
            }
        }
    }
}

// =======================================================================
// host launch
// =======================================================================
extern "C" void kernel_launch(void* const* d_in, const int* in_sizes, int n_in,
                              void* d_out, int out_size)
{
    const float* x      = (const float*)d_in[0];
    const float* ctx    = (const float*)d_in[1];
    const float* gn1_g  = (const float*)d_in[2];
    const float* gn1_b  = (const float*)d_in[3];
    const float* w_in   = (const float*)d_in[4];
    const float* b_in   = (const float*)d_in[5];
    const float* sa_wk  = (const float*)d_in[6];
    const float* sa_wq  = (const float*)d_in[7];
    const float* sa_wv  = (const float*)d_in[8];
    const float* sa_wp  = (const float*)d_in[9];
    const float* sa_gng = (const float*)d_in[10];
    const float* sa_gnb = (const float*)d_in[11];
    const float* ca_wq  = (const float*)d_in[12];
    const float* ca_wk  = (const float*)d_in[13];
    const float* ca_wv  = (const float*)d_in[14];
    const float* ca_wo  = (const float*)d_in[15];
    const float* ca_bo  = (const float*)d_in[16];
    const float* w_out  = (const float*)d_in[17];
    const float* b_out  = (const float*)d_in[18];
    float* out = (float*)d_out;

    float *p_gn1, *p_h, *p_hn, *p_q, *p_k, *p_v, *p_sim, *p_o, *p_k2, *p_wr;
    cudaGetSymbolAddress((void**)&p_gn1, g_gn1);
    cudaGetSymbolAddress((void**)&p_h,   g_h);
    cudaGetSymbolAddress((void**)&p_hn,  g_hn);
    cudaGetSymbolAddress((void**)&p_q,   g_q);
    cudaGetSymbolAddress((void**)&p_k,   g_k);
    cudaGetSymbolAddress((void**)&p_v,   g_v);
    cudaGetSymbolAddress((void**)&p_sim, g_sim);
    cudaGetSymbolAddress((void**)&p_o,   g_o);
    cudaGetSymbolAddress((void**)&p_k2,  g_k2);
    cudaGetSymbolAddress((void**)&p_wr,  g_wr);

    cudaFuncSetAttribute(gemm_mma<0>, cudaFuncAttributeMaxDynamicSharedMemorySize, SMEM_MMA);
    cudaFuncSetAttribute(gemm_mma<1>, cudaFuncAttributeMaxDynamicSharedMemorySize, SMEM_MMA);
    cudaFuncSetAttribute(gn1_kernel,  cudaFuncAttributeMaxDynamicSharedMemorySize, 32768);
    cudaFuncSetAttribute(gn2_kernel,  cudaFuncAttributeMaxDynamicSharedMemorySize, 65536);

    const float simScale = 0.044194173824159216f; // 512^-0.5

    // 0. pre-round weights
    wround_kernel<<<WTOT/1024, 1024>>>(w_in, sa_wq, sa_wk, sa_wv, sa_wp,
                                       ca_wq, ca_wk, ca_wv, ca_wo, w_out, p_wr);

    // 1. GroupNorm1 -> token-major (rounded)
    gn1_kernel<<<BATCH*32, 256, 32768>>>(x, gn1_g, gn1_b, p_gn1);

    // 2. conv_in: h = gn1 @ w_in^T + b_in (full precision store)
    gemm_mma<0><<<dim3(4,128,1), 256, SMEM_MMA>>>(p_gn1, p_wr+OFF_WIN, p_h, b_in, nullptr, nullptr,
        MTOK, CIN, CIN, CIN, INNER, INNER, INNER, 1.f, EP_STORE, 0, 1, 0,0, 0,0, 0,0);

    // 3. SA groupnorm (rounded)
    gn2_kernel<<<BATCH*32, 256, 65536>>>(p_h, sa_gng, sa_gnb, p_hn);

    // 4. q/k/v projections (rounded; v stored transposed per batch)
    gemm_mma<0><<<dim3(4,128,1), 256, SMEM_MMA>>>(p_hn, p_wr+OFF_SAQ, p_q, nullptr, nullptr, nullptr,
        MTOK, INNER, INNER, INNER, INNER, INNER, INNER, 1.f, EP_STORE, 1, 1, 0,0, 0,0, 0,0);
    gemm_mma<0><<<dim3(4,128,1), 256, SMEM_MMA>>>(p_hn, p_wr+OFF_SAK, p_k, nullptr, nullptr, nullptr,
        MTOK, INNER, INNER, INNER, INNER, INNER, INNER, 1.f, EP_STORE, 1, 1, 0,0, 0,0, 0,0);
    gemm_mma<0><<<dim3(4,128,1), 256, SMEM_MMA>>>(p_hn, p_wr+OFF_SAV, p_v, nullptr, nullptr, nullptr,
        MTOK, INNER, INNER, INNER, INNER, INNER, INNER, 1.f, EP_STORET, 1, 1, 0,0, 0,0, 0,0);

    // 5. sim = scale * q @ k^T (batched; full precision, softmax rounds)
    gemm_mma<0><<<dim3(8,8,BATCH), 256, SMEM_MMA>>>(p_q, p_k, p_sim, nullptr, nullptr, nullptr,
        NTOK, INNER, INNER, INNER, NTOK, NTOK, NTOK, simScale, EP_STORE, 0, 1,
        (long long)NTOK*INNER, 0, (long long)NTOK*INNER, 0, (long long)NTOK*NTOK, 0);

    // 6. SA softmax (rounded)
    softmax_rows<<<MTOK, 256>>>(p_sim);

    // 7. o = P @ vT^T (batched NT; rounded)
    gemm_mma<0><<<dim3(4,8,BATCH), 256, SMEM_MMA>>>(p_sim, p_v, p_o, nullptr, nullptr, nullptr,
        NTOK, NTOK, NTOK, NTOK, INNER, INNER, INNER, 1.f, EP_STORE, 1, 1,
        (long long)NTOK*NTOK, 0, (long long)INNER*NTOK, 0, (long long)NTOK*INNER, 0);

    // 8. h = 2*h + o @ sa_wp^T (full precision)
    gemm_mma<0><<<dim3(4,128,1), 256, SMEM_MMA>>>(p_o, p_wr+OFF_SAP, p_h, nullptr, nullptr, nullptr,
        MTOK, INNER, INNER, INNER, INNER, INNER, INNER, 1.f, EP_RES2, 0, 1, 0,0, 0,0, 0,0);

    // 9. CA q = h @ ca_wq^T (A unrounded -> CVTA; rounded store)
    gemm_mma<1><<<dim3(4,128,1), 256, SMEM_MMA>>>(p_h, p_wr+OFF_CAQ, p_q, nullptr, nullptr, nullptr,
        MTOK, INNER, INNER, INNER, INNER, INNER, INNER, 1.f, EP_STORE, 1, 1, 0,0, 0,0, 0,0);

    // 10/11. CA k (rounded), v (per-head transposed into g_v, rounded)
    gemm_mma<1><<<dim3(4,10,1), 256, SMEM_MMA>>>(ctx, p_wr+OFF_CAK, p_k2, nullptr, nullptr, nullptr,
        MCTX, CTXD, CTXD, CTXD, INNER, INNER, INNER, 1.f, EP_STORE, 1, 1, 0,0, 0,0, 0,0);
    gemm_mma<1><<<dim3(4,10,1), 256, SMEM_MMA>>>(ctx, p_wr+OFF_CAV, p_v, nullptr, nullptr, nullptr,
        MCTX, CTXD, CTXD, CTXD, INNER, INNER, INNER, 1.f, EP_STORECV, 1, 1, 0,0, 0,0, 0,0);

    // 12. CA sim2 = 0.125 * Q_head @ K2_head^T  [128 batches of (1024 x 77 x 64)]
    gemm_mma<0><<<dim3(1,8,128), 256, SMEM_MMA>>>(p_q, p_k2, p_sim, nullptr, nullptr, nullptr,
        NTOK, 64, INNER, INNER, 96, CTXN, CTXN, 0.125f, EP_STORE, 0, 8,
        (long long)NTOK*INNER, 64, (long long)CTXN*INNER, 64,
        (long long)8*NTOK*96, (long long)NTOK*96);

    // 13. CA softmax over 77 (rounded, zero-pads to 96)
    softmax77<<<16384, 256>>>(p_sim);

    // 14. CA o = P @ v2t^T  [128 batches of (1024 x 64 x 96)] (rounded)
    gemm_mma<0><<<dim3(1,8,128), 256, SMEM_MMA>>>(p_sim, p_v, p_o, nullptr, nullptr, nullptr,
        NTOK, 96, 96, 96, INNER, 64, 64, 1.f, EP_STORE, 1, 8,
        (long long)8*NTOK*96, (long long)NTOK*96, (long long)8*64*96, (long long)64*96,
        (long long)NTOK*INNER, 64);

    // 15. h = h + (o @ ca_wo^T + ca_bo) (full precision)
    gemm_mma<0><<<dim3(4,128,1), 256, SMEM_MMA>>>(p_o, p_wr+OFF_CAO, p_h, ca_bo, nullptr, nullptr,
        MTOK, INNER, INNER, INNER, INNER, INNER, INNER, 1.f, EP_RES1, 0, 1, 0,0, 0,0, 0,0);

    // 16. out = transpose(h @ w_out^T + b_out) + x (A unrounded -> CVTA)
    gemm_mma<1><<<dim3(2,128,1), 256, SMEM_MMA>>>(p_h, p_wr+OFF_WOUT, nullptr, b_out, x, out,
        MTOK, INNER, INNER, INNER, CIN, CIN, CIN, 1.f, EP_TRANSX, 0, 1, 0,0, 0,0, 0,0);
}